// round 1
// baseline (speedup 1.0000x reference)
#include <cuda_runtime.h>
#include <cstdint>

// Problem constants (upper bounds for static scratch)
#define MAX_NODES  100000
#define MAX_EDGES  1600000
#define HIDDEN     128
#define MAX_GRAPHS 256

// ---------------------------------------------------------------------------
// Static device scratch (no allocation allowed in kernel_launch)
// ---------------------------------------------------------------------------
__device__ float g_A[MAX_NODES * HIDDEN];   // GEMM output  (h = X @ W)
__device__ float g_B[MAX_NODES * HIDDEN];   // aggregation buffer
__device__ float g_deg[MAX_NODES];          // in-degree count (float)
__device__ float g_dis[MAX_NODES];          // (1+deg)^-0.5
__device__ float g_inv[MAX_NODES];          // 1/(1+deg)
__device__ float g_psum[MAX_GRAPHS];        // pooled dot-product sums
__device__ float g_pcnt[MAX_GRAPHS];        // per-graph node counts

// ---------------------------------------------------------------------------
// Small utility kernels
// ---------------------------------------------------------------------------
__global__ void zero_deg_kernel(int n) {
    int i = blockIdx.x * blockDim.x + threadIdx.x;
    if (i < n) g_deg[i] = 0.0f;
}

__global__ void zero_pool_kernel(int nG) {
    int i = blockIdx.x * blockDim.x + threadIdx.x;
    if (i < nG) { g_psum[i] = 0.0f; g_pcnt[i] = 0.0f; }
}

__global__ void degree_kernel(const int* __restrict__ dst, int nE) {
    int e = blockIdx.x * blockDim.x + threadIdx.x;
    if (e < nE) atomicAdd(&g_deg[dst[e]], 1.0f);
}

__global__ void deg_transform_kernel(int n) {
    int i = blockIdx.x * blockDim.x + threadIdx.x;
    if (i < n) {
        float d = 1.0f + g_deg[i];
        g_dis[i] = rsqrtf(d);
        g_inv[i] = 1.0f / d;
    }
}

// ---------------------------------------------------------------------------
// GEMM: H = pre(X) @ W  (K = 128, N(cols) = 128), fused epilogue:
//   A[row] = H[row]
//   B[row] = H[row] * inv_deg[row]   (self-loop init of the aggregation buffer)
// pre(X) = relu(X + bias_in) when PRE (layer-2 input activation), else identity.
// Tile: 32 rows/block, 128 threads, TM=8 x TN=4 register blocking,
// W staged in shared in two 64-K chunks (stays under 48 KB static smem).
// ---------------------------------------------------------------------------
template <bool PRE>
__global__ void __launch_bounds__(128)
gemm_kernel(const float* __restrict__ X, const float* __restrict__ W,
            const float* __restrict__ bias_in,
            float* __restrict__ A, float* __restrict__ Bo, int n)
{
    __shared__ float Ws[64 * 132];   // [kk][col], row stride 132 (528B, 16B-aligned)
    __shared__ float Xs[32 * 68];    // [r][kk],  row stride 68  (272B, 16B-aligned)

    const int tid = threadIdx.x;
    const int tx  = tid & 31;        // column group: cols tx*4 .. tx*4+3
    const int ty  = tid >> 5;        // row group: rows ty*8 .. ty*8+7
    const int row0 = blockIdx.x * 32;

    float acc[8][4];
#pragma unroll
    for (int r = 0; r < 8; r++)
#pragma unroll
        for (int c = 0; c < 4; c++) acc[r][c] = 0.0f;

    for (int kc = 0; kc < 128; kc += 64) {
        // ---- stage W chunk: 64 x 128 floats ----
#pragma unroll
        for (int j = 0; j < 16; j++) {
            int i  = tid + j * 128;        // 0..2047 float4 index
            int kk = i >> 5, c4 = i & 31;
            float4 w = reinterpret_cast<const float4*>(W)[(kc + kk) * 32 + c4];
            *reinterpret_cast<float4*>(&Ws[kk * 132 + c4 * 4]) = w;
        }
        // ---- stage X chunk: 32 rows x 64 k ----
#pragma unroll
        for (int j = 0; j < 4; j++) {
            int i  = tid + j * 128;        // 0..511 float4 index
            int r  = i >> 4, c4 = i & 15;
            int row = row0 + r;
            float4 v = make_float4(0.f, 0.f, 0.f, 0.f);
            if (row < n)
                v = reinterpret_cast<const float4*>(X)[row * 32 + (kc >> 2) + c4];
            if (PRE) {
                float4 bb = reinterpret_cast<const float4*>(bias_in)[(kc >> 2) + c4];
                v.x = fmaxf(v.x + bb.x, 0.f);
                v.y = fmaxf(v.y + bb.y, 0.f);
                v.z = fmaxf(v.z + bb.z, 0.f);
                v.w = fmaxf(v.w + bb.w, 0.f);
            }
            *reinterpret_cast<float4*>(&Xs[r * 68 + c4 * 4]) = v;
        }
        __syncthreads();

        // ---- compute: 64 k per chunk, blocked by 4 ----
#pragma unroll 4
        for (int kk = 0; kk < 64; kk += 4) {
            float4 w0 = *reinterpret_cast<const float4*>(&Ws[(kk + 0) * 132 + tx * 4]);
            float4 w1 = *reinterpret_cast<const float4*>(&Ws[(kk + 1) * 132 + tx * 4]);
            float4 w2 = *reinterpret_cast<const float4*>(&Ws[(kk + 2) * 132 + tx * 4]);
            float4 w3 = *reinterpret_cast<const float4*>(&Ws[(kk + 3) * 132 + tx * 4]);
#pragma unroll
            for (int r = 0; r < 8; r++) {
                float4 xv = *reinterpret_cast<const float4*>(&Xs[(ty * 8 + r) * 68 + kk]);
                acc[r][0] += xv.x * w0.x + xv.y * w1.x + xv.z * w2.x + xv.w * w3.x;
                acc[r][1] += xv.x * w0.y + xv.y * w1.y + xv.z * w2.y + xv.w * w3.y;
                acc[r][2] += xv.x * w0.z + xv.y * w1.z + xv.z * w2.z + xv.w * w3.z;
                acc[r][3] += xv.x * w0.w + xv.y * w1.w + xv.z * w2.w + xv.w * w3.w;
            }
        }
        __syncthreads();
    }

    // ---- epilogue: write H to A, H*inv_deg to B ----
#pragma unroll
    for (int r = 0; r < 8; r++) {
        int row = row0 + ty * 8 + r;
        if (row < n) {
            float4 v = make_float4(acc[r][0], acc[r][1], acc[r][2], acc[r][3]);
            reinterpret_cast<float4*>(A)[row * 32 + tx] = v;
            float iv = g_inv[row];
            float4 u = make_float4(v.x * iv, v.y * iv, v.z * iv, v.w * iv);
            reinterpret_cast<float4*>(Bo)[row * 32 + tx] = u;
        }
    }
}

// ---------------------------------------------------------------------------
// Edge scatter: B[dst] += A[src] * (dis[src]*dis[dst]).
// One warp per edge; float4 gather + one red.global.add.v4.f32 per lane.
// ---------------------------------------------------------------------------
__global__ void __launch_bounds__(256)
scatter_kernel(const int* __restrict__ src, const int* __restrict__ dst,
               const float* __restrict__ A, float* __restrict__ Bo, int nE)
{
    int wid  = (blockIdx.x * blockDim.x + threadIdx.x) >> 5;
    int lane = threadIdx.x & 31;
    if (wid >= nE) return;

    int s = __ldg(&src[wid]);
    int d = __ldg(&dst[wid]);
    float c = g_dis[s] * g_dis[d];

    float4 v = __ldg(&reinterpret_cast<const float4*>(A)[s * 32 + lane]);
    float* p = Bo + (size_t)d * 128 + lane * 4;
    asm volatile("red.global.add.v4.f32 [%0], {%1,%2,%3,%4};"
                 :: "l"(p), "f"(v.x * c), "f"(v.y * c), "f"(v.z * c), "f"(v.w * c)
                 : "memory");
}

// ---------------------------------------------------------------------------
// Pool: per node  s = dot(relu(B[node] + b2), Wfc); atomic into graph bins.
// One warp per node.
// ---------------------------------------------------------------------------
__global__ void __launch_bounds__(256)
pool_kernel(const float* __restrict__ Bo, const float* __restrict__ b2,
            const float* __restrict__ Wfc, const int* __restrict__ batch, int n)
{
    int wid  = (blockIdx.x * blockDim.x + threadIdx.x) >> 5;
    int lane = threadIdx.x & 31;
    if (wid >= n) return;

    float4 v  = reinterpret_cast<const float4*>(Bo)[wid * 32 + lane];
    float4 bb = __ldg(&reinterpret_cast<const float4*>(b2)[lane]);
    float4 w  = __ldg(&reinterpret_cast<const float4*>(Wfc)[lane]);

    float p = fmaxf(v.x + bb.x, 0.f) * w.x
            + fmaxf(v.y + bb.y, 0.f) * w.y
            + fmaxf(v.z + bb.z, 0.f) * w.z
            + fmaxf(v.w + bb.w, 0.f) * w.w;
#pragma unroll
    for (int o = 16; o; o >>= 1) p += __shfl_xor_sync(0xffffffffu, p, o);

    if (lane == 0) {
        int g = __ldg(&batch[wid]);
        atomicAdd(&g_psum[g], p);
        atomicAdd(&g_pcnt[g], 1.0f);
    }
}

__global__ void final_kernel(const float* __restrict__ bfc, float* __restrict__ out, int nG)
{
    int g = blockIdx.x * blockDim.x + threadIdx.x;
    if (g < nG) out[g] = g_psum[g] / fmaxf(g_pcnt[g], 1.0f) + bfc[0];
}

// ---------------------------------------------------------------------------
// Launch
// ---------------------------------------------------------------------------
extern "C" void kernel_launch(void* const* d_in, const int* in_sizes, int n_in,
                              void* d_out, int out_size)
{
    const float* x    = (const float*)d_in[0];
    const int*   ei   = (const int*)  d_in[1];
    const int*   batch= (const int*)  d_in[2];
    const float* W1   = (const float*)d_in[3];
    const float* b1   = (const float*)d_in[4];
    const float* W2   = (const float*)d_in[5];
    const float* b2   = (const float*)d_in[6];
    const float* Wfc  = (const float*)d_in[7];
    const float* bfc  = (const float*)d_in[8];
    float*       out  = (float*)d_out;

    const int n  = in_sizes[2];          // n_nodes (batch vector length)
    const int nE = in_sizes[1] / 2;      // edge count
    const int nG = out_size;             // n_graphs

    const int* src = ei;
    const int* dst = ei + nE;

    float *A, *B;
    cudaGetSymbolAddress((void**)&A, g_A);
    cudaGetSymbolAddress((void**)&B, g_B);

    const int T = 256;

    // degrees
    zero_deg_kernel<<<(n + T - 1) / T, T>>>(n);
    degree_kernel<<<(nE + T - 1) / T, T>>>(dst, nE);
    deg_transform_kernel<<<(n + T - 1) / T, T>>>(n);

    // layer 1: A = x@W1 ; B = A*inv_deg ; B += scatter(A)
    gemm_kernel<false><<<(n + 31) / 32, 128>>>(x, W1, nullptr, A, B, n);
    scatter_kernel<<<(nE + 7) / 8, T>>>(src, dst, A, B, nE);

    // layer 2: A = relu(B+b1)@W2 ; B = A*inv_deg ; B += scatter(A)
    gemm_kernel<true><<<(n + 31) / 32, 128>>>(B, W2, b1, A, B, n);
    scatter_kernel<<<(nE + 7) / 8, T>>>(src, dst, A, B, nE);

    // pooled regression head
    zero_pool_kernel<<<1, T>>>(nG);
    pool_kernel<<<(n + 7) / 8, T>>>(B, b2, Wfc, batch, n);
    final_kernel<<<(nG + T - 1) / T, T>>>(bfc, out, nG);
}

// round 2
// speedup vs baseline: 1.5358x; 1.5358x over previous
#include <cuda_runtime.h>
#include <cstdint>

#define MAX_NODES  100000
#define MAX_EDGES  1600000
#define HIDDEN     128
#define MAX_GRAPHS 256

// ---------------------------------------------------------------------------
// Static device scratch
// ---------------------------------------------------------------------------
__device__ float g_A[MAX_NODES * HIDDEN];   // A' = (X@W) * dis  (row-scaled GEMM out)
__device__ float g_B[MAX_NODES * HIDDEN];   // aggregated output per layer
__device__ float g_dis[MAX_NODES];          // (1+deg)^-0.5
__device__ int   g_cnt[MAX_NODES];          // in-degree counts (histogram)
__device__ int   g_off[MAX_NODES + 1];      // CSR offsets (by dst)
__device__ int   g_cur[MAX_NODES];          // fill cursors
__device__ int   g_esrc[MAX_EDGES];         // CSR column indices (src per dst-segment)
__device__ float g_psum[MAX_GRAPHS];
__device__ float g_pcnt[MAX_GRAPHS];

// ---------------------------------------------------------------------------
// Init: zero histogram + pool bins
// ---------------------------------------------------------------------------
__global__ void init_kernel(int n, int nG) {
    int i = blockIdx.x * blockDim.x + threadIdx.x;
    if (i < n) g_cnt[i] = 0;
    if (i < nG) { g_psum[i] = 0.0f; g_pcnt[i] = 0.0f; }
}

__global__ void hist_kernel(const int* __restrict__ dst, int nE) {
    int e = blockIdx.x * blockDim.x + threadIdx.x;
    if (e < nE) atomicAdd(&g_cnt[dst[e]], 1);
}

__global__ void deg_transform_kernel(int n) {
    int i = blockIdx.x * blockDim.x + threadIdx.x;
    if (i < n) g_dis[i] = rsqrtf(1.0f + (float)g_cnt[i]);
}

// ---------------------------------------------------------------------------
// Single-block exclusive scan of g_cnt -> g_off / g_cur  (n up to 100k)
// ---------------------------------------------------------------------------
__global__ void __launch_bounds__(1024)
scan_kernel(int n) {
    __shared__ int wsum[32];
    const int tid = threadIdx.x, lane = tid & 31, wid = tid >> 5;
    int running = 0;
    for (int base = 0; base < n; base += 1024) {
        int i = base + tid;
        int v = (i < n) ? g_cnt[i] : 0;
        int x = v;
#pragma unroll
        for (int o = 1; o < 32; o <<= 1) {
            int y = __shfl_up_sync(0xffffffffu, x, o);
            if (lane >= o) x += y;
        }
        if (lane == 31) wsum[wid] = x;
        __syncthreads();
        if (wid == 0) {
            int s = wsum[lane];
#pragma unroll
            for (int o = 1; o < 32; o <<= 1) {
                int y = __shfl_up_sync(0xffffffffu, s, o);
                if (lane >= o) s += y;
            }
            wsum[lane] = s;   // inclusive scan of warp sums
        }
        __syncthreads();
        int woff = (wid > 0) ? wsum[wid - 1] : 0;
        int excl = running + woff + x - v;
        if (i < n) { g_off[i] = excl; g_cur[i] = excl; }
        running += wsum[31];
        __syncthreads();
    }
    if (tid == 0) g_off[n] = running;
}

__global__ void fill_kernel(const int* __restrict__ src, const int* __restrict__ dst, int nE) {
    int e = blockIdx.x * blockDim.x + threadIdx.x;
    if (e < nE) {
        int p = atomicAdd(&g_cur[dst[e]], 1);
        g_esrc[p] = src[e];
    }
}

// ---------------------------------------------------------------------------
// GEMM: H = pre(X) @ W  (K=128, 128 cols), epilogue writes A' = H * dis[row].
// pre(X) = relu(X + bias_in) when PRE.  32 rows/block, 128 thr, TM=8 x TN=4.
// ---------------------------------------------------------------------------
template <bool PRE>
__global__ void __launch_bounds__(128)
gemm_kernel(const float* __restrict__ X, const float* __restrict__ W,
            const float* __restrict__ bias_in, float* __restrict__ A, int n)
{
    __shared__ float Ws[64 * 132];
    __shared__ float Xs[32 * 68];

    const int tid = threadIdx.x;
    const int tx  = tid & 31;
    const int ty  = tid >> 5;
    const int row0 = blockIdx.x * 32;

    float acc[8][4];
#pragma unroll
    for (int r = 0; r < 8; r++)
#pragma unroll
        for (int c = 0; c < 4; c++) acc[r][c] = 0.0f;

    for (int kc = 0; kc < 128; kc += 64) {
#pragma unroll
        for (int j = 0; j < 16; j++) {
            int i  = tid + j * 128;
            int kk = i >> 5, c4 = i & 31;
            float4 w = reinterpret_cast<const float4*>(W)[(kc + kk) * 32 + c4];
            *reinterpret_cast<float4*>(&Ws[kk * 132 + c4 * 4]) = w;
        }
#pragma unroll
        for (int j = 0; j < 4; j++) {
            int i  = tid + j * 128;
            int r  = i >> 4, c4 = i & 15;
            int row = row0 + r;
            float4 v = make_float4(0.f, 0.f, 0.f, 0.f);
            if (row < n)
                v = reinterpret_cast<const float4*>(X)[row * 32 + (kc >> 2) + c4];
            if (PRE) {
                float4 bb = reinterpret_cast<const float4*>(bias_in)[(kc >> 2) + c4];
                v.x = fmaxf(v.x + bb.x, 0.f);
                v.y = fmaxf(v.y + bb.y, 0.f);
                v.z = fmaxf(v.z + bb.z, 0.f);
                v.w = fmaxf(v.w + bb.w, 0.f);
            }
            *reinterpret_cast<float4*>(&Xs[r * 68 + c4 * 4]) = v;
        }
        __syncthreads();

#pragma unroll 4
        for (int kk = 0; kk < 64; kk += 4) {
            float4 w0 = *reinterpret_cast<const float4*>(&Ws[(kk + 0) * 132 + tx * 4]);
            float4 w1 = *reinterpret_cast<const float4*>(&Ws[(kk + 1) * 132 + tx * 4]);
            float4 w2 = *reinterpret_cast<const float4*>(&Ws[(kk + 2) * 132 + tx * 4]);
            float4 w3 = *reinterpret_cast<const float4*>(&Ws[(kk + 3) * 132 + tx * 4]);
#pragma unroll
            for (int r = 0; r < 8; r++) {
                float4 xv = *reinterpret_cast<const float4*>(&Xs[(ty * 8 + r) * 68 + kk]);
                acc[r][0] += xv.x * w0.x + xv.y * w1.x + xv.z * w2.x + xv.w * w3.x;
                acc[r][1] += xv.x * w0.y + xv.y * w1.y + xv.z * w2.y + xv.w * w3.y;
                acc[r][2] += xv.x * w0.z + xv.y * w1.z + xv.z * w2.z + xv.w * w3.z;
                acc[r][3] += xv.x * w0.w + xv.y * w1.w + xv.z * w2.w + xv.w * w3.w;
            }
        }
        __syncthreads();
    }

#pragma unroll
    for (int r = 0; r < 8; r++) {
        int row = row0 + ty * 8 + r;
        if (row < n) {
            float ds = g_dis[row];
            float4 v = make_float4(acc[r][0] * ds, acc[r][1] * ds,
                                   acc[r][2] * ds, acc[r][3] * ds);
            reinterpret_cast<float4*>(A)[row * 32 + tx] = v;
        }
    }
}

// ---------------------------------------------------------------------------
// Gather: B[d] = dis[d] * ( A'[d] + sum_{e in CSR(d)} A'[src_e] )
// One warp per node; edge loop unrolled x4 for MLP.
// ---------------------------------------------------------------------------
__global__ void __launch_bounds__(256)
gather_kernel(const float* __restrict__ Ap, float* __restrict__ Bo, int n)
{
    int node = (blockIdx.x * blockDim.x + threadIdx.x) >> 5;
    int lane = threadIdx.x & 31;
    if (node >= n) return;

    const int beg = g_off[node], end = g_off[node + 1];
    const float4* __restrict__ A4 = reinterpret_cast<const float4*>(Ap);

    float4 acc = A4[(size_t)node * 32 + lane];   // self-loop term

    int i = beg;
    for (; i + 4 <= end; i += 4) {
        int s0 = g_esrc[i], s1 = g_esrc[i + 1], s2 = g_esrc[i + 2], s3 = g_esrc[i + 3];
        float4 v0 = __ldg(&A4[(size_t)s0 * 32 + lane]);
        float4 v1 = __ldg(&A4[(size_t)s1 * 32 + lane]);
        float4 v2 = __ldg(&A4[(size_t)s2 * 32 + lane]);
        float4 v3 = __ldg(&A4[(size_t)s3 * 32 + lane]);
        acc.x += (v0.x + v1.x) + (v2.x + v3.x);
        acc.y += (v0.y + v1.y) + (v2.y + v3.y);
        acc.z += (v0.z + v1.z) + (v2.z + v3.z);
        acc.w += (v0.w + v1.w) + (v2.w + v3.w);
    }
    for (; i < end; i++) {
        float4 v = __ldg(&A4[(size_t)g_esrc[i] * 32 + lane]);
        acc.x += v.x; acc.y += v.y; acc.z += v.z; acc.w += v.w;
    }

    float ds = g_dis[node];
    acc.x *= ds; acc.y *= ds; acc.z *= ds; acc.w *= ds;
    reinterpret_cast<float4*>(Bo)[(size_t)node * 32 + lane] = acc;
}

// ---------------------------------------------------------------------------
// Pool head: per node s = dot(relu(B[node]+b2), Wfc), atomic into graph bins.
// ---------------------------------------------------------------------------
__global__ void __launch_bounds__(256)
pool_kernel(const float* __restrict__ Bo, const float* __restrict__ b2,
            const float* __restrict__ Wfc, const int* __restrict__ batch, int n)
{
    int node = (blockIdx.x * blockDim.x + threadIdx.x) >> 5;
    int lane = threadIdx.x & 31;
    if (node >= n) return;

    float4 v  = reinterpret_cast<const float4*>(Bo)[(size_t)node * 32 + lane];
    float4 bb = __ldg(&reinterpret_cast<const float4*>(b2)[lane]);
    float4 w  = __ldg(&reinterpret_cast<const float4*>(Wfc)[lane]);

    float p = fmaxf(v.x + bb.x, 0.f) * w.x
            + fmaxf(v.y + bb.y, 0.f) * w.y
            + fmaxf(v.z + bb.z, 0.f) * w.z
            + fmaxf(v.w + bb.w, 0.f) * w.w;
#pragma unroll
    for (int o = 16; o; o >>= 1) p += __shfl_xor_sync(0xffffffffu, p, o);

    if (lane == 0) {
        int g = __ldg(&batch[node]);
        atomicAdd(&g_psum[g], p);
        atomicAdd(&g_pcnt[g], 1.0f);
    }
}

__global__ void final_kernel(const float* __restrict__ bfc, float* __restrict__ out, int nG)
{
    int g = blockIdx.x * blockDim.x + threadIdx.x;
    if (g < nG) out[g] = g_psum[g] / fmaxf(g_pcnt[g], 1.0f) + bfc[0];
}

// ---------------------------------------------------------------------------
// Launch
// ---------------------------------------------------------------------------
extern "C" void kernel_launch(void* const* d_in, const int* in_sizes, int n_in,
                              void* d_out, int out_size)
{
    const float* x     = (const float*)d_in[0];
    const int*   ei    = (const int*)  d_in[1];
    const int*   batch = (const int*)  d_in[2];
    const float* W1    = (const float*)d_in[3];
    const float* b1    = (const float*)d_in[4];
    const float* W2    = (const float*)d_in[5];
    const float* b2    = (const float*)d_in[6];
    const float* Wfc   = (const float*)d_in[7];
    const float* bfc   = (const float*)d_in[8];
    float*       out   = (float*)d_out;

    const int n  = in_sizes[2];
    const int nE = in_sizes[1] / 2;
    const int nG = out_size;

    const int* src = ei;
    const int* dst = ei + nE;

    float *A, *B;
    cudaGetSymbolAddress((void**)&A, g_A);
    cudaGetSymbolAddress((void**)&B, g_B);

    const int T = 256;

    // CSR build (by dst) + degree normalization
    init_kernel<<<(n + T - 1) / T, T>>>(n, nG);
    hist_kernel<<<(nE + T - 1) / T, T>>>(dst, nE);
    deg_transform_kernel<<<(n + T - 1) / T, T>>>(n);
    scan_kernel<<<1, 1024>>>(n);
    fill_kernel<<<(nE + T - 1) / T, T>>>(src, dst, nE);

    // layer 1
    gemm_kernel<false><<<(n + 31) / 32, 128>>>(x, W1, nullptr, A, n);
    gather_kernel<<<(n + 7) / 8, T>>>(A, B, n);

    // layer 2
    gemm_kernel<true><<<(n + 31) / 32, 128>>>(B, W2, b1, A, n);
    gather_kernel<<<(n + 7) / 8, T>>>(A, B, n);

    // pooled regression head
    pool_kernel<<<(n + 7) / 8, T>>>(B, b2, Wfc, batch, n);
    final_kernel<<<(nG + T - 1) / T, T>>>(bfc, out, nG);
}